// round 13
// baseline (speedup 1.0000x reference)
#include <cuda_runtime.h>
#include <math.h>

#define TT     256   // B*S tiles
#define NTOK   256   // N tokens per tile
#define DMODEL 512
#define NH     8
#define HD     64

typedef unsigned long long u64t;

// ---------------- f32x2 packed-math helpers (B300 FFMA2 path) ---------------
__device__ __forceinline__ u64t pack2(float lo, float hi) {
    u64t r; asm("mov.b64 %0, {%1,%2};" : "=l"(r) : "f"(lo), "f"(hi)); return r;
}
__device__ __forceinline__ void fma2(u64t& d, u64t a, u64t b) {
    asm("fma.rn.f32x2 %0, %1, %2, %0;" : "+l"(d) : "l"(a), "l"(b));
}
__device__ __forceinline__ float2 unpack2(u64t v) {
    float2 f; asm("mov.b64 {%0,%1}, %2;" : "=f"(f.x), "=f"(f.y) : "l"(v)); return f;
}

// ---------------- scratch (device globals: no allocation allowed) -----------
__device__ float g_Q[TT * DMODEL];          // q per tile (with bias)
__device__ float g_P[TT * NH * DMODEL];     // [t][h][d], pre-scaled by 1/8
__device__ float g_Y[TT * NH * DMODEL];     // [t][h][d], softmax-weighted x sums
__device__ float g_ctx[TT * DMODEL];        // concat heads per tile

// ------------- register-blocked GEMM: C = A @ B + bias ----------------------
// 32x64 tile, 256 threads, 2x4 micro-tile per thread. (unchanged from R12)
__global__ __launch_bounds__(256) void gemm_k(
    const float* __restrict__ A, size_t a_stride, size_t a_zoff,
    const float* __restrict__ B, int b_stride, int b_zoff,
    const float* __restrict__ bias, int bias_zoff,
    float* __restrict__ C, int c_stride, int c_zoff,
    int Kdim)
{
    __shared__ __align__(16) u64t  Atp[2][32 * 34];
    __shared__ __align__(16) float Bs[2][32 * 64];
    int tid = threadIdx.x;
    int tx = tid & 15, ty = tid >> 4;
    int t0 = blockIdx.x * 32;
    int n0 = blockIdx.y * 64;
    int z  = blockIdx.z;

    const float* Ab    = A + (size_t)z * a_zoff;
    const float* Bb    = B + (size_t)z * b_zoff + n0;
    const float* biasb = bias + (size_t)z * bias_zoff + n0;
    float*       Cb    = C + (size_t)z * c_zoff + n0;

    int arow = tid >> 3, akq = tid & 7;
    const float* Aptr = Ab + (size_t)(t0 + arow) * a_stride + akq * 4;
    int br0 = tid >> 4, bc0 = (tid & 15) * 4;
    const float* Bptr = Bb + (size_t)br0 * b_stride + bc0;

    float4 pa, pb0, pb1;
    pa  = *(const float4*)(Aptr);
    pb0 = *(const float4*)(Bptr);
    pb1 = *(const float4*)(Bptr + (size_t)16 * b_stride);
    Atp[0][(akq * 4 + 0) * 34 + arow] = pack2(pa.x, pa.x);
    Atp[0][(akq * 4 + 1) * 34 + arow] = pack2(pa.y, pa.y);
    Atp[0][(akq * 4 + 2) * 34 + arow] = pack2(pa.z, pa.z);
    Atp[0][(akq * 4 + 3) * 34 + arow] = pack2(pa.w, pa.w);
    *(float4*)&Bs[0][br0 * 64 + bc0]        = pb0;
    *(float4*)&Bs[0][(br0 + 16) * 64 + bc0] = pb1;
    __syncthreads();

    u64t a00 = 0ull, a01 = 0ull, a10 = 0ull, a11 = 0ull;
    int nch = Kdim >> 5;
    for (int c = 0; c < nch; c++) {
        int cur = c & 1;
        if (c + 1 < nch) {
            const float* Ap = Aptr + (c + 1) * 32;
            const float* Bp = Bptr + (size_t)(c + 1) * 32 * b_stride;
            pa  = *(const float4*)(Ap);
            pb0 = *(const float4*)(Bp);
            pb1 = *(const float4*)(Bp + (size_t)16 * b_stride);
        }
        const u64t*  Ar = &Atp[cur][ty * 2];
        const float* Br = &Bs[cur][tx * 4];
        #pragma unroll
        for (int kk = 0; kk < 32; kk++) {
            ulonglong2 av = *(const ulonglong2*)&Ar[kk * 34];
            ulonglong2 bv = *(const ulonglong2*)&Br[kk * 64];
            fma2(a00, av.x, bv.x); fma2(a01, av.x, bv.y);
            fma2(a10, av.y, bv.x); fma2(a11, av.y, bv.y);
        }
        if (c + 1 < nch) {
            int nxt = cur ^ 1;
            Atp[nxt][(akq * 4 + 0) * 34 + arow] = pack2(pa.x, pa.x);
            Atp[nxt][(akq * 4 + 1) * 34 + arow] = pack2(pa.y, pa.y);
            Atp[nxt][(akq * 4 + 2) * 34 + arow] = pack2(pa.z, pa.z);
            Atp[nxt][(akq * 4 + 3) * 34 + arow] = pack2(pa.w, pa.w);
            *(float4*)&Bs[nxt][br0 * 64 + bc0]        = pb0;
            *(float4*)&Bs[nxt][(br0 + 16) * 64 + bc0] = pb1;
        }
        __syncthreads();
    }
    float4 bb = *(const float4*)&biasb[tx * 4];
    float2 r00 = unpack2(a00), r01 = unpack2(a01);
    float2 r10 = unpack2(a10), r11 = unpack2(a11);
    float4 o0 = make_float4(r00.x + bb.x, r00.y + bb.y, r01.x + bb.z, r01.y + bb.w);
    float4 o1 = make_float4(r10.x + bb.x, r10.y + bb.y, r11.x + bb.z, r11.y + bb.w);
    *(float4*)&Cb[(size_t)(t0 + ty * 2)     * c_stride + tx * 4] = o0;
    *(float4*)&Cb[(size_t)(t0 + ty * 2 + 1) * c_stride + tx * 4] = o1;
}

// ---- K2: P[t,h,d] = 0.125 * sum_j Q[t,h*64+j] * Wk[d, h*64+j] --------------
// CTA = (64-d block, head). Wk slice staged ONCE, reused across all 16 t-blocks.
__global__ __launch_bounds__(256) void pproj_k(const float* __restrict__ Wk, int z0)
{
    __shared__ float Bt[64 * 68];        // transposed Wk slice, padded
    __shared__ float As[2][16 * 64];     // double-buffered Q slices
    int tid = threadIdx.x;
    int tx = tid & 15, ty = tid >> 4;
    int d0 = blockIdx.x * 64;
    int h  = blockIdx.y + z0;

    #pragma unroll
    for (int it = 0; it < 16; it++) {
        int i = tid + it * 256;
        int dd = i >> 6, j = i & 63;
        Bt[j * 68 + dd] = Wk[(size_t)(d0 + dd) * DMODEL + h * HD + j];
    }
    // stage tb=0 Q slice
    {
        int r = tid >> 6, j = tid & 63;
        #pragma unroll
        for (int it = 0; it < 4; it++)
            As[0][(r + it * 4) * 64 + j] =
                g_Q[(size_t)(r + it * 4) * DMODEL + h * HD + j];
    }
    __syncthreads();

    for (int tb = 0; tb < 16; tb++) {
        int cur = tb & 1;
        // prefetch next t-block's Q into the other buffer
        if (tb + 1 < 16) {
            int r = tid >> 6, j = tid & 63;
            int nxt = cur ^ 1;
            #pragma unroll
            for (int it = 0; it < 4; it++)
                As[nxt][(r + it * 4) * 64 + j] =
                    g_Q[(size_t)((tb + 1) * 16 + r + it * 4) * DMODEL + h * HD + j];
        }
        float4 acc = make_float4(0.f, 0.f, 0.f, 0.f);
        #pragma unroll
        for (int j = 0; j < 64; j++) {
            float a  = As[cur][ty * 64 + j];
            float4 b = *reinterpret_cast<const float4*>(&Bt[j * 68 + tx * 4]);
            acc.x += a * b.x; acc.y += a * b.y;
            acc.z += a * b.z; acc.w += a * b.w;
        }
        const float s = 0.125f;
        float4 o = make_float4(acc.x * s, acc.y * s, acc.z * s, acc.w * s);
        *reinterpret_cast<float4*>(
            &g_P[((size_t)(tb * 16 + ty) * NH + h) * DMODEL + d0 + tx * 4]) = o;
        __syncthreads();
    }
}

// ---------------- K3: per-tile attention: logits -> softmax -> Y ------------
__global__ __launch_bounds__(256) void attn_k(const float* __restrict__ x,
                                              const float* __restrict__ bk)
{
    // pool phase1: [ Psp 16KB | xs 16.4KB ]; phase2: [ Es2 16KB | Ls 8KB ]
    __shared__ __align__(16) unsigned char pool[16384 + 16 * 257 * 4];
    u64t*       Psp = (u64t*)pool;                  // [512][4] f32x2 head-pairs
    float*      xs  = (float*)(pool + 16384);       // [16][257] transposed chunk
    ulonglong2* Es2 = (ulonglong2*)pool;            // [4][256] dup'd exp pairs
    float*      Ls  = (float*)(pool + 16384);       // [8][256] logits
    __shared__ float red[18];

    int tid = threadIdx.x;
    int t = blockIdx.x;
    const float* xt = x + (size_t)t * NTOK * DMODEL;

    // stage P pre-packed as f32x2 head-pairs (coalesced on d)
    const float* Pt = g_P + (size_t)t * NH * DMODEL;
    #pragma unroll
    for (int it = 0; it < 8; it++) {
        int i = tid + it * 256;
        int d = i & 511, pp = i >> 9;
        float lo = Pt[(size_t)(2 * pp)     * DMODEL + d];
        float hi = Pt[(size_t)(2 * pp + 1) * DMODEL + d];
        Psp[d * 4 + pp] = pack2(lo, hi);
    }
    // c[h] = 0.125 * q_h . bk_h   (warp per head)
    {
        int h = tid >> 5, j = tid & 31;
        const float* Qt  = g_Q + (size_t)t * DMODEL + h * HD;
        const float* bkh = bk + h * HD;
        float p = Qt[j] * bkh[j] + Qt[j + 32] * bkh[j + 32];
        #pragma unroll
        for (int o = 16; o > 0; o >>= 1) p += __shfl_down_sync(0xffffffffu, p, o);
        if (j == 0) red[h] = 0.125f * p;
    }
    __syncthreads();

    u64t la[4];
    #pragma unroll
    for (int pp = 0; pp < 4; pp++) la[pp] = pack2(red[2 * pp], red[2 * pp + 1]);

    // ---- phase 1: thread = token; 16-d chunks, reg-prefetched staging
    int srow = tid >> 2, sf4 = tid & 3;   // rows srow+{0,64,128,192}, f4 = sf4
    const float4* xt4 = reinterpret_cast<const float4*>(xt);
    float4 v0 = xt4[(size_t)(srow      ) * 128 + sf4];
    float4 v1 = xt4[(size_t)(srow +  64) * 128 + sf4];
    float4 v2 = xt4[(size_t)(srow + 128) * 128 + sf4];
    float4 v3 = xt4[(size_t)(srow + 192) * 128 + sf4];

    for (int c0 = 0; c0 < DMODEL; c0 += 16) {
        int dl0 = sf4 * 4;
        xs[(dl0 + 0) * 257 + srow      ] = v0.x;
        xs[(dl0 + 1) * 257 + srow      ] = v0.y;
        xs[(dl0 + 2) * 257 + srow      ] = v0.z;
        xs[(dl0 + 3) * 257 + srow      ] = v0.w;
        xs[(dl0 + 0) * 257 + srow +  64] = v1.x;
        xs[(dl0 + 1) * 257 + srow +  64] = v1.y;
        xs[(dl0 + 2) * 257 + srow +  64] = v1.z;
        xs[(dl0 + 3) * 257 + srow +  64] = v1.w;
        xs[(dl0 + 0) * 257 + srow + 128] = v2.x;
        xs[(dl0 + 1) * 257 + srow + 128] = v2.y;
        xs[(dl0 + 2) * 257 + srow + 128] = v2.z;
        xs[(dl0 + 3) * 257 + srow + 128] = v2.w;
        xs[(dl0 + 0) * 257 + srow + 192] = v3.x;
        xs[(dl0 + 1) * 257 + srow + 192] = v3.y;
        xs[(dl0 + 2) * 257 + srow + 192] = v3.z;
        xs[(dl0 + 3) * 257 + srow + 192] = v3.w;
        __syncthreads();
        if (c0 + 16 < DMODEL) {   // prefetch NEXT chunk; latency hides under FMA2
            int f = ((c0 + 16) >> 2) + sf4;
            v0 = xt4[(size_t)(srow      ) * 128 + f];
            v1 = xt4[(size_t)(srow +  64) * 128 + f];
            v2 = xt4[(size_t)(srow + 128) * 128 + f];
            v3 = xt4[(size_t)(srow + 192) * 128 + f];
        }
        #pragma unroll
        for (int dl = 0; dl < 16; dl++) {
            float xv = xs[dl * 257 + tid];                 // conflict-free
            u64t xd = pack2(xv, xv);
            const ulonglong2* Pp =
                reinterpret_cast<const ulonglong2*>(&Psp[(c0 + dl) * 4]);
            ulonglong2 p0 = Pp[0], p1 = Pp[1];             // broadcast LDS.128
            fma2(la[0], xd, p0.x); fma2(la[1], xd, p0.y);
            fma2(la[2], xd, p1.x); fma2(la[3], xd, p1.y);
        }
        __syncthreads();
    }
    float l[8];
    #pragma unroll
    for (int pp = 0; pp < 4; pp++) {
        float2 f = unpack2(la[pp]);
        l[2 * pp] = f.x; l[2 * pp + 1] = f.y;
    }

    // ---- softmax (xs/Psp dead; Ls/Es2 live)
    #pragma unroll
    for (int h = 0; h < 8; h++) Ls[h * 256 + tid] = l[h];
    __syncthreads();

    int wid = tid >> 5, lane = tid & 31;
    {   // max per head (warp per head)
        float m = -1e30f;
        for (int i = lane; i < 256; i += 32) m = fmaxf(m, Ls[wid * 256 + i]);
        #pragma unroll
        for (int o = 16; o > 0; o >>= 1)
            m = fmaxf(m, __shfl_xor_sync(0xffffffffu, m, o));
        if (lane == 0) red[wid] = m;
    }
    __syncthreads();
    #pragma unroll
    for (int j = 0; j < 4; j++) {
        float e0 = __expf(l[2 * j]     - red[2 * j]);
        float e1 = __expf(l[2 * j + 1] - red[2 * j + 1]);
        ulonglong2 v; v.x = pack2(e0, e0); v.y = pack2(e1, e1);
        Es2[j * 256 + tid] = v;                        // conflict-free STS.128
    }
    __syncthreads();
    {   // sum per head -> 1/s
        int j = wid >> 1, hi = wid & 1;
        float s = 0.f;
        for (int i = lane; i < 256; i += 32) {
            ulonglong2 v = Es2[j * 256 + i];
            s += unpack2(hi ? v.y : v.x).x;
        }
        #pragma unroll
        for (int o = 16; o > 0; o >>= 1) s += __shfl_xor_sync(0xffffffffu, s, o);
        if (lane == 0) red[8 + wid] = 1.0f / s;
    }
    __syncthreads();

    // ---- phase 2: Y[h,d] = (1/s) sum_n e[h,n] x[n,d]; thread owns 2 columns
    u64t acc[8];
    #pragma unroll
    for (int h = 0; h < 8; h++) acc[h] = 0ull;
    const float2* x2 = reinterpret_cast<const float2*>(xt) + tid;
    #pragma unroll 8
    for (int nn = 0; nn < NTOK; nn++) {
        float2 xv = x2[(size_t)nn * 256];              // coalesced, L2-hit
        u64t xp = pack2(xv.x, xv.y);
        ulonglong2 e0 = Es2[0 * 256 + nn];             // broadcast LDS.128
        ulonglong2 e1 = Es2[1 * 256 + nn];
        ulonglong2 e2 = Es2[2 * 256 + nn];
        ulonglong2 e3 = Es2[3 * 256 + nn];
        fma2(acc[0], e0.x, xp); fma2(acc[1], e0.y, xp);
        fma2(acc[2], e1.x, xp); fma2(acc[3], e1.y, xp);
        fma2(acc[4], e2.x, xp); fma2(acc[5], e2.y, xp);
        fma2(acc[6], e3.x, xp); fma2(acc[7], e3.y, xp);
    }
    #pragma unroll
    for (int h = 0; h < 8; h++) {
        float inv = red[8 + h];
        float2 a = unpack2(acc[h]);
        float2 o; o.x = a.x * inv; o.y = a.y * inv;
        reinterpret_cast<float2*>(g_Y + ((size_t)t * NH + h) * DMODEL)[tid] = o;
    }
}

// ---------------------------------------------------------------------------
extern "C" void kernel_launch(void* const* d_in, const int* in_sizes, int n_in,
                              void* d_out, int out_size)
{
    const float* x  = (const float*)d_in[0];
    const float* Wq = (const float*)d_in[1];
    const float* bq = (const float*)d_in[2];
    const float* Wk = (const float*)d_in[3];
    const float* bk = (const float*)d_in[4];
    const float* Wv = (const float*)d_in[5];
    const float* bv = (const float*)d_in[6];
    const float* Wo = (const float*)d_in[7];
    const float* bo = (const float*)d_in[8];
    float* out = (float*)d_out;
    (void)in_sizes; (void)n_in; (void)out_size;

    void *pQ, *pY, *pC;
    cudaGetSymbolAddress(&pQ, g_Q);
    cudaGetSymbolAddress(&pY, g_Y);
    cudaGetSymbolAddress(&pC, g_ctx);

    // mine #0: K1: Q = X0 @ Wq + bq
    gemm_k<<<dim3(8, 8, 1), 256>>>(
        x, (size_t)(NTOK * DMODEL), 0,
        Wq, DMODEL, 0, bq, 0,
        (float*)pQ, DMODEL, 0, DMODEL);

    // mine #1-#3: K2 split 3/3/2 heads (puts attn at my index 4 -> ncu -s 5)
    pproj_k<<<dim3(8, 3), 256>>>(Wk, 0);
    pproj_k<<<dim3(8, 3), 256>>>(Wk, 3);
    pproj_k<<<dim3(8, 2), 256>>>(Wk, 6);

    // mine #4: K3: per-tile attention -> g_Y
    attn_k<<<TT, 256>>>(x, bk);

    // mine #5: K4: ctx_h = Y_h @ Wv[:,h] + bv_h
    gemm_k<<<dim3(8, 1, NH), 256>>>(
        (const float*)pY, (size_t)(NH * DMODEL), (size_t)DMODEL,
        Wv, DMODEL, HD, bv, HD,
        (float*)pC, DMODEL, HD, DMODEL);

    // mine #6: K5: out = ctx @ Wo + bo
    gemm_k<<<dim3(8, 8, 1), 256>>>(
        (const float*)pC, (size_t)DMODEL, 0,
        Wo, DMODEL, 0, bo, 0,
        out, DMODEL, 0, DMODEL);
}

// round 14
// speedup vs baseline: 1.3966x; 1.3966x over previous
#include <cuda_runtime.h>
#include <math.h>

#define TT     256   // B*S tiles
#define NTOK   256   // N tokens per tile
#define DMODEL 512
#define NH     8
#define HD     64

typedef unsigned long long u64t;

// ---------------- f32x2 packed-math helpers (B300 FFMA2 path) ---------------
__device__ __forceinline__ u64t pack2(float lo, float hi) {
    u64t r; asm("mov.b64 %0, {%1,%2};" : "=l"(r) : "f"(lo), "f"(hi)); return r;
}
__device__ __forceinline__ void fma2(u64t& d, u64t a, u64t b) {
    asm("fma.rn.f32x2 %0, %1, %2, %0;" : "+l"(d) : "l"(a), "l"(b));
}
__device__ __forceinline__ float2 unpack2(u64t v) {
    float2 f; asm("mov.b64 {%0,%1}, %2;" : "=f"(f.x), "=f"(f.y) : "l"(v)); return f;
}

// ---------------- scratch (device globals: no allocation allowed) -----------
__device__ float g_Q[TT * DMODEL];          // q per tile (with bias)
__device__ float g_P[TT * NH * DMODEL];     // [t][h][d], pre-scaled by 1/8
__device__ float g_Y[TT * NH * DMODEL];     // [t][h][d], softmax-weighted x sums
__device__ float g_ctx[TT * DMODEL];        // concat heads per tile

// ------------- register-blocked GEMM: C = A @ B + bias ----------------------
// 32x64 tile, 256 threads, 2x4 micro-tile per thread.
__global__ __launch_bounds__(256) void gemm_k(
    const float* __restrict__ A, size_t a_stride, size_t a_zoff,
    const float* __restrict__ B, int b_stride, int b_zoff,
    const float* __restrict__ bias, int bias_zoff,
    float* __restrict__ C, int c_stride, int c_zoff,
    int Kdim)
{
    __shared__ __align__(16) u64t  Atp[2][32 * 34];
    __shared__ __align__(16) float Bs[2][32 * 64];
    int tid = threadIdx.x;
    int tx = tid & 15, ty = tid >> 4;
    int t0 = blockIdx.x * 32;
    int n0 = blockIdx.y * 64;
    int z  = blockIdx.z;

    const float* Ab    = A + (size_t)z * a_zoff;
    const float* Bb    = B + (size_t)z * b_zoff + n0;
    const float* biasb = bias + (size_t)z * bias_zoff + n0;
    float*       Cb    = C + (size_t)z * c_zoff + n0;

    int arow = tid >> 3, akq = tid & 7;
    const float* Aptr = Ab + (size_t)(t0 + arow) * a_stride + akq * 4;
    int br0 = tid >> 4, bc0 = (tid & 15) * 4;
    const float* Bptr = Bb + (size_t)br0 * b_stride + bc0;

    float4 pa, pb0, pb1;
    pa  = *(const float4*)(Aptr);
    pb0 = *(const float4*)(Bptr);
    pb1 = *(const float4*)(Bptr + (size_t)16 * b_stride);
    Atp[0][(akq * 4 + 0) * 34 + arow] = pack2(pa.x, pa.x);
    Atp[0][(akq * 4 + 1) * 34 + arow] = pack2(pa.y, pa.y);
    Atp[0][(akq * 4 + 2) * 34 + arow] = pack2(pa.z, pa.z);
    Atp[0][(akq * 4 + 3) * 34 + arow] = pack2(pa.w, pa.w);
    *(float4*)&Bs[0][br0 * 64 + bc0]        = pb0;
    *(float4*)&Bs[0][(br0 + 16) * 64 + bc0] = pb1;
    __syncthreads();

    u64t a00 = 0ull, a01 = 0ull, a10 = 0ull, a11 = 0ull;
    int nch = Kdim >> 5;
    for (int c = 0; c < nch; c++) {
        int cur = c & 1;
        if (c + 1 < nch) {
            const float* Ap = Aptr + (c + 1) * 32;
            const float* Bp = Bptr + (size_t)(c + 1) * 32 * b_stride;
            pa  = *(const float4*)(Ap);
            pb0 = *(const float4*)(Bp);
            pb1 = *(const float4*)(Bp + (size_t)16 * b_stride);
        }
        const u64t*  Ar = &Atp[cur][ty * 2];
        const float* Br = &Bs[cur][tx * 4];
        #pragma unroll
        for (int kk = 0; kk < 32; kk++) {
            ulonglong2 av = *(const ulonglong2*)&Ar[kk * 34];
            ulonglong2 bv = *(const ulonglong2*)&Br[kk * 64];
            fma2(a00, av.x, bv.x); fma2(a01, av.x, bv.y);
            fma2(a10, av.y, bv.x); fma2(a11, av.y, bv.y);
        }
        if (c + 1 < nch) {
            int nxt = cur ^ 1;
            Atp[nxt][(akq * 4 + 0) * 34 + arow] = pack2(pa.x, pa.x);
            Atp[nxt][(akq * 4 + 1) * 34 + arow] = pack2(pa.y, pa.y);
            Atp[nxt][(akq * 4 + 2) * 34 + arow] = pack2(pa.z, pa.z);
            Atp[nxt][(akq * 4 + 3) * 34 + arow] = pack2(pa.w, pa.w);
            *(float4*)&Bs[nxt][br0 * 64 + bc0]        = pb0;
            *(float4*)&Bs[nxt][(br0 + 16) * 64 + bc0] = pb1;
        }
        __syncthreads();
    }
    float4 bb = *(const float4*)&biasb[tx * 4];
    float2 r00 = unpack2(a00), r01 = unpack2(a01);
    float2 r10 = unpack2(a10), r11 = unpack2(a11);
    float4 o0 = make_float4(r00.x + bb.x, r00.y + bb.y, r01.x + bb.z, r01.y + bb.w);
    float4 o1 = make_float4(r10.x + bb.x, r10.y + bb.y, r11.x + bb.z, r11.y + bb.w);
    *(float4*)&Cb[(size_t)(t0 + ty * 2)     * c_stride + tx * 4] = o0;
    *(float4*)&Cb[(size_t)(t0 + ty * 2 + 1) * c_stride + tx * 4] = o1;
}

// ---- K2: P[t,h,d] = 0.125 * sum_j Q[t,h*64+j] * Wk[d, h*64+j] --------------
// R12 parallel form: CTA = (16-t block, 64-d block, head). grid 16*8*heads.
__global__ __launch_bounds__(256) void pproj_k(const float* __restrict__ Wk, int z0)
{
    __shared__ float As[16 * 64];
    __shared__ float Bt[64 * 68];
    int tid = threadIdx.x;
    int tx = tid & 15, ty = tid >> 4;
    int t0 = blockIdx.x * 16;
    int d0 = blockIdx.y * 64;
    int h  = blockIdx.z + z0;

    #pragma unroll
    for (int it = 0; it < 4; it++) {
        int i = tid + it * 256;
        int r = i >> 6, j = i & 63;
        As[i] = g_Q[(size_t)(t0 + r) * DMODEL + h * HD + j];
    }
    #pragma unroll
    for (int it = 0; it < 16; it++) {
        int i = tid + it * 256;
        int dd = i >> 6, j = i & 63;
        Bt[j * 68 + dd] = Wk[(size_t)(d0 + dd) * DMODEL + h * HD + j];
    }
    __syncthreads();

    float4 acc = make_float4(0.f, 0.f, 0.f, 0.f);
    #pragma unroll
    for (int j = 0; j < 64; j++) {
        float a  = As[ty * 64 + j];
        float4 b = *reinterpret_cast<const float4*>(&Bt[j * 68 + tx * 4]);
        acc.x += a * b.x; acc.y += a * b.y;
        acc.z += a * b.z; acc.w += a * b.w;
    }
    const float s = 0.125f;
    float4 o = make_float4(acc.x * s, acc.y * s, acc.z * s, acc.w * s);
    *reinterpret_cast<float4*>(
        &g_P[((size_t)(t0 + ty) * NH + h) * DMODEL + d0 + tx * 4]) = o;
}

// ---------------- K3: per-tile attention: logits -> softmax -> Y ------------
__global__ __launch_bounds__(256) void attn_k(const float* __restrict__ x,
                                              const float* __restrict__ bk)
{
    // pool phase1: [ Psp 16KB | xs 16.4KB ]; phase2: [ Es2 16KB | Ls 8KB ]
    __shared__ __align__(16) unsigned char pool[16384 + 16 * 257 * 4];
    u64t*       Psp = (u64t*)pool;                  // [512][4] f32x2 head-pairs
    float*      xs  = (float*)(pool + 16384);       // [16][257] transposed chunk
    ulonglong2* Es2 = (ulonglong2*)pool;            // [4][256] dup'd exp pairs
    float*      Ls  = (float*)(pool + 16384);       // [8][256] logits
    __shared__ float red[18];

    int tid = threadIdx.x;
    int t = blockIdx.x;
    const float* xt = x + (size_t)t * NTOK * DMODEL;

    // stage P pre-packed as f32x2 head-pairs (coalesced on d)
    const float* Pt = g_P + (size_t)t * NH * DMODEL;
    #pragma unroll
    for (int it = 0; it < 8; it++) {
        int i = tid + it * 256;
        int d = i & 511, pp = i >> 9;
        float lo = Pt[(size_t)(2 * pp)     * DMODEL + d];
        float hi = Pt[(size_t)(2 * pp + 1) * DMODEL + d];
        Psp[d * 4 + pp] = pack2(lo, hi);
    }
    // c[h] = 0.125 * q_h . bk_h   (warp per head)
    {
        int h = tid >> 5, j = tid & 31;
        const float* Qt  = g_Q + (size_t)t * DMODEL + h * HD;
        const float* bkh = bk + h * HD;
        float p = Qt[j] * bkh[j] + Qt[j + 32] * bkh[j + 32];
        #pragma unroll
        for (int o = 16; o > 0; o >>= 1) p += __shfl_down_sync(0xffffffffu, p, o);
        if (j == 0) red[h] = 0.125f * p;
    }
    __syncthreads();

    u64t la[4];
    #pragma unroll
    for (int pp = 0; pp < 4; pp++) la[pp] = pack2(red[2 * pp], red[2 * pp + 1]);

    // ---- phase 1: thread = token; 16-d chunks, reg-prefetched staging
    int srow = tid >> 2, sf4 = tid & 3;   // rows srow+{0,64,128,192}, f4 = sf4
    const float4* xt4 = reinterpret_cast<const float4*>(xt);
    float4 v0 = xt4[(size_t)(srow      ) * 128 + sf4];
    float4 v1 = xt4[(size_t)(srow +  64) * 128 + sf4];
    float4 v2 = xt4[(size_t)(srow + 128) * 128 + sf4];
    float4 v3 = xt4[(size_t)(srow + 192) * 128 + sf4];

    for (int c0 = 0; c0 < DMODEL; c0 += 16) {
        int dl0 = sf4 * 4;
        xs[(dl0 + 0) * 257 + srow      ] = v0.x;
        xs[(dl0 + 1) * 257 + srow      ] = v0.y;
        xs[(dl0 + 2) * 257 + srow      ] = v0.z;
        xs[(dl0 + 3) * 257 + srow      ] = v0.w;
        xs[(dl0 + 0) * 257 + srow +  64] = v1.x;
        xs[(dl0 + 1) * 257 + srow +  64] = v1.y;
        xs[(dl0 + 2) * 257 + srow +  64] = v1.z;
        xs[(dl0 + 3) * 257 + srow +  64] = v1.w;
        xs[(dl0 + 0) * 257 + srow + 128] = v2.x;
        xs[(dl0 + 1) * 257 + srow + 128] = v2.y;
        xs[(dl0 + 2) * 257 + srow + 128] = v2.z;
        xs[(dl0 + 3) * 257 + srow + 128] = v2.w;
        xs[(dl0 + 0) * 257 + srow + 192] = v3.x;
        xs[(dl0 + 1) * 257 + srow + 192] = v3.y;
        xs[(dl0 + 2) * 257 + srow + 192] = v3.z;
        xs[(dl0 + 3) * 257 + srow + 192] = v3.w;
        __syncthreads();
        if (c0 + 16 < DMODEL) {   // prefetch NEXT chunk; hides under FMA2 block
            int f = ((c0 + 16) >> 2) + sf4;
            v0 = xt4[(size_t)(srow      ) * 128 + f];
            v1 = xt4[(size_t)(srow +  64) * 128 + f];
            v2 = xt4[(size_t)(srow + 128) * 128 + f];
            v3 = xt4[(size_t)(srow + 192) * 128 + f];
        }
        #pragma unroll
        for (int dl = 0; dl < 16; dl++) {
            float xv = xs[dl * 257 + tid];                 // conflict-free
            u64t xd = pack2(xv, xv);
            const ulonglong2* Pp =
                reinterpret_cast<const ulonglong2*>(&Psp[(c0 + dl) * 4]);
            ulonglong2 p0 = Pp[0], p1 = Pp[1];             // broadcast LDS.128
            fma2(la[0], xd, p0.x); fma2(la[1], xd, p0.y);
            fma2(la[2], xd, p1.x); fma2(la[3], xd, p1.y);
        }
        __syncthreads();
    }
    float l[8];
    #pragma unroll
    for (int pp = 0; pp < 4; pp++) {
        float2 f = unpack2(la[pp]);
        l[2 * pp] = f.x; l[2 * pp + 1] = f.y;
    }

    // ---- softmax (xs/Psp dead; Ls/Es2 live)
    #pragma unroll
    for (int h = 0; h < 8; h++) Ls[h * 256 + tid] = l[h];
    __syncthreads();

    int wid = tid >> 5, lane = tid & 31;
    {   // max per head (warp per head)
        float m = -1e30f;
        for (int i = lane; i < 256; i += 32) m = fmaxf(m, Ls[wid * 256 + i]);
        #pragma unroll
        for (int o = 16; o > 0; o >>= 1)
            m = fmaxf(m, __shfl_xor_sync(0xffffffffu, m, o));
        if (lane == 0) red[wid] = m;
    }
    __syncthreads();
    #pragma unroll
    for (int j = 0; j < 4; j++) {
        float e0 = __expf(l[2 * j]     - red[2 * j]);
        float e1 = __expf(l[2 * j + 1] - red[2 * j + 1]);
        ulonglong2 v; v.x = pack2(e0, e0); v.y = pack2(e1, e1);
        Es2[j * 256 + tid] = v;                        // conflict-free STS.128
    }
    __syncthreads();
    {   // sum per head -> 1/s
        int j = wid >> 1, hi = wid & 1;
        float s = 0.f;
        for (int i = lane; i < 256; i += 32) {
            ulonglong2 v = Es2[j * 256 + i];
            s += unpack2(hi ? v.y : v.x).x;
        }
        #pragma unroll
        for (int o = 16; o > 0; o >>= 1) s += __shfl_xor_sync(0xffffffffu, s, o);
        if (lane == 0) red[8 + wid] = 1.0f / s;
    }
    __syncthreads();

    // ---- phase 2: Y[h,d] = (1/s) sum_n e[h,n] x[n,d]; thread owns 2 columns
    u64t acc[8];
    #pragma unroll
    for (int h = 0; h < 8; h++) acc[h] = 0ull;
    const float2* x2 = reinterpret_cast<const float2*>(xt) + tid;
    #pragma unroll 8
    for (int nn = 0; nn < NTOK; nn++) {
        float2 xv = x2[(size_t)nn * 256];              // coalesced, L2-hit
        u64t xp = pack2(xv.x, xv.y);
        ulonglong2 e0 = Es2[0 * 256 + nn];             // broadcast LDS.128
        ulonglong2 e1 = Es2[1 * 256 + nn];
        ulonglong2 e2 = Es2[2 * 256 + nn];
        ulonglong2 e3 = Es2[3 * 256 + nn];
        fma2(acc[0], e0.x, xp); fma2(acc[1], e0.y, xp);
        fma2(acc[2], e1.x, xp); fma2(acc[3], e1.y, xp);
        fma2(acc[4], e2.x, xp); fma2(acc[5], e2.y, xp);
        fma2(acc[6], e3.x, xp); fma2(acc[7], e3.y, xp);
    }
    #pragma unroll
    for (int h = 0; h < 8; h++) {
        float inv = red[8 + h];
        float2 a = unpack2(acc[h]);
        float2 o; o.x = a.x * inv; o.y = a.y * inv;
        reinterpret_cast<float2*>(g_Y + ((size_t)t * NH + h) * DMODEL)[tid] = o;
    }
}

// ---------------------------------------------------------------------------
extern "C" void kernel_launch(void* const* d_in, const int* in_sizes, int n_in,
                              void* d_out, int out_size)
{
    const float* x  = (const float*)d_in[0];
    const float* Wq = (const float*)d_in[1];
    const float* bq = (const float*)d_in[2];
    const float* Wk = (const float*)d_in[3];
    const float* bk = (const float*)d_in[4];
    const float* Wv = (const float*)d_in[5];
    const float* bv = (const float*)d_in[6];
    const float* Wo = (const float*)d_in[7];
    const float* bo = (const float*)d_in[8];
    float* out = (float*)d_out;
    (void)in_sizes; (void)n_in; (void)out_size;

    void *pQ, *pY, *pC;
    cudaGetSymbolAddress(&pQ, g_Q);
    cudaGetSymbolAddress(&pY, g_Y);
    cudaGetSymbolAddress(&pC, g_ctx);

    // mine #0: K1: Q = X0 @ Wq + bq
    gemm_k<<<dim3(8, 8, 1), 256>>>(
        x, (size_t)(NTOK * DMODEL), 0,
        Wq, DMODEL, 0, bq, 0,
        (float*)pQ, DMODEL, 0, DMODEL);

    // mine #1, #2: K2 split 4+4 heads, 512 CTAs each
    pproj_k<<<dim3(16, 8, 4), 256>>>(Wk, 0);
    pproj_k<<<dim3(16, 8, 4), 256>>>(Wk, 4);

    // mine #3: K3: per-tile attention -> g_Y   (ncu -s 5 with 2 hidden
    // pre-launches captures THIS launch)
    attn_k<<<TT, 256>>>(x, bk);

    // mine #4: K4: ctx_h = Y_h @ Wv[:,h] + bv_h
    gemm_k<<<dim3(8, 1, NH), 256>>>(
        (const float*)pY, (size_t)(NH * DMODEL), (size_t)DMODEL,
        Wv, DMODEL, HD, bv, HD,
        (float*)pC, DMODEL, HD, DMODEL);

    // mine #5: K5: out = ctx @ Wo + bo
    gemm_k<<<dim3(8, 8, 1), 256>>>(
        (const float*)pC, (size_t)DMODEL, 0,
        Wo, DMODEL, 0, bo, 0,
        out, DMODEL, 0, DMODEL);
}

// round 15
// speedup vs baseline: 1.5043x; 1.0771x over previous
#include <cuda_runtime.h>
#include <math.h>

#define TT     256   // B*S tiles
#define NTOK   256   // N tokens per tile
#define DMODEL 512
#define NH     8
#define HD     64

typedef unsigned long long u64t;

// ---------------- f32x2 packed-math helpers (B300 FFMA2 path) ---------------
__device__ __forceinline__ u64t pack2(float lo, float hi) {
    u64t r; asm("mov.b64 %0, {%1,%2};" : "=l"(r) : "f"(lo), "f"(hi)); return r;
}
__device__ __forceinline__ void fma2(u64t& d, u64t a, u64t b) {
    asm("fma.rn.f32x2 %0, %1, %2, %0;" : "+l"(d) : "l"(a), "l"(b));
}
__device__ __forceinline__ float2 unpack2(u64t v) {
    float2 f; asm("mov.b64 {%0,%1}, %2;" : "=f"(f.x), "=f"(f.y) : "l"(v)); return f;
}

// ---------------- scratch (device globals: no allocation allowed) -----------
__device__ float g_Q[TT * DMODEL];          // q per tile (with bias)
__device__ float g_P[TT * NH * DMODEL];     // [t][h][d], pre-scaled by 1/8
__device__ float g_Y[TT * NH * DMODEL];     // [t][h][d], softmax-weighted x sums
__device__ float g_ctx[TT * DMODEL];        // concat heads per tile

// ------------- register-blocked GEMM: C = A @ B + bias ----------------------
__global__ __launch_bounds__(256) void gemm_k(
    const float* __restrict__ A, size_t a_stride, size_t a_zoff,
    const float* __restrict__ B, int b_stride, int b_zoff,
    const float* __restrict__ bias, int bias_zoff,
    float* __restrict__ C, int c_stride, int c_zoff,
    int Kdim)
{
    __shared__ __align__(16) u64t  Atp[2][32 * 34];
    __shared__ __align__(16) float Bs[2][32 * 64];
    int tid = threadIdx.x;
    int tx = tid & 15, ty = tid >> 4;
    int t0 = blockIdx.x * 32;
    int n0 = blockIdx.y * 64;
    int z  = blockIdx.z;

    const float* Ab    = A + (size_t)z * a_zoff;
    const float* Bb    = B + (size_t)z * b_zoff + n0;
    const float* biasb = bias + (size_t)z * bias_zoff + n0;
    float*       Cb    = C + (size_t)z * c_zoff + n0;

    int arow = tid >> 3, akq = tid & 7;
    const float* Aptr = Ab + (size_t)(t0 + arow) * a_stride + akq * 4;
    int br0 = tid >> 4, bc0 = (tid & 15) * 4;
    const float* Bptr = Bb + (size_t)br0 * b_stride + bc0;

    float4 pa, pb0, pb1;
    pa  = *(const float4*)(Aptr);
    pb0 = *(const float4*)(Bptr);
    pb1 = *(const float4*)(Bptr + (size_t)16 * b_stride);
    Atp[0][(akq * 4 + 0) * 34 + arow] = pack2(pa.x, pa.x);
    Atp[0][(akq * 4 + 1) * 34 + arow] = pack2(pa.y, pa.y);
    Atp[0][(akq * 4 + 2) * 34 + arow] = pack2(pa.z, pa.z);
    Atp[0][(akq * 4 + 3) * 34 + arow] = pack2(pa.w, pa.w);
    *(float4*)&Bs[0][br0 * 64 + bc0]        = pb0;
    *(float4*)&Bs[0][(br0 + 16) * 64 + bc0] = pb1;
    __syncthreads();

    u64t a00 = 0ull, a01 = 0ull, a10 = 0ull, a11 = 0ull;
    int nch = Kdim >> 5;
    for (int c = 0; c < nch; c++) {
        int cur = c & 1;
        if (c + 1 < nch) {
            const float* Ap = Aptr + (c + 1) * 32;
            const float* Bp = Bptr + (size_t)(c + 1) * 32 * b_stride;
            pa  = *(const float4*)(Ap);
            pb0 = *(const float4*)(Bp);
            pb1 = *(const float4*)(Bp + (size_t)16 * b_stride);
        }
        const u64t*  Ar = &Atp[cur][ty * 2];
        const float* Br = &Bs[cur][tx * 4];
        #pragma unroll
        for (int kk = 0; kk < 32; kk++) {
            ulonglong2 av = *(const ulonglong2*)&Ar[kk * 34];
            ulonglong2 bv = *(const ulonglong2*)&Br[kk * 64];
            fma2(a00, av.x, bv.x); fma2(a01, av.x, bv.y);
            fma2(a10, av.y, bv.x); fma2(a11, av.y, bv.y);
        }
        if (c + 1 < nch) {
            int nxt = cur ^ 1;
            Atp[nxt][(akq * 4 + 0) * 34 + arow] = pack2(pa.x, pa.x);
            Atp[nxt][(akq * 4 + 1) * 34 + arow] = pack2(pa.y, pa.y);
            Atp[nxt][(akq * 4 + 2) * 34 + arow] = pack2(pa.z, pa.z);
            Atp[nxt][(akq * 4 + 3) * 34 + arow] = pack2(pa.w, pa.w);
            *(float4*)&Bs[nxt][br0 * 64 + bc0]        = pb0;
            *(float4*)&Bs[nxt][(br0 + 16) * 64 + bc0] = pb1;
        }
        __syncthreads();
    }
    float4 bb = *(const float4*)&biasb[tx * 4];
    float2 r00 = unpack2(a00), r01 = unpack2(a01);
    float2 r10 = unpack2(a10), r11 = unpack2(a11);
    float4 o0 = make_float4(r00.x + bb.x, r00.y + bb.y, r01.x + bb.z, r01.y + bb.w);
    float4 o1 = make_float4(r10.x + bb.x, r10.y + bb.y, r11.x + bb.z, r11.y + bb.w);
    *(float4*)&Cb[(size_t)(t0 + ty * 2)     * c_stride + tx * 4] = o0;
    *(float4*)&Cb[(size_t)(t0 + ty * 2 + 1) * c_stride + tx * 4] = o1;
}

// ---- K2: P[t,h,d] = 0.125 * sum_j Q[t,h*64+j] * Wk[d, h*64+j] --------------
__global__ __launch_bounds__(256) void pproj_k(const float* __restrict__ Wk, int z0)
{
    __shared__ float As[16 * 64];
    __shared__ float Bt[64 * 68];
    int tid = threadIdx.x;
    int tx = tid & 15, ty = tid >> 4;
    int t0 = blockIdx.x * 16;
    int d0 = blockIdx.y * 64;
    int h  = blockIdx.z + z0;

    #pragma unroll
    for (int it = 0; it < 4; it++) {
        int i = tid + it * 256;
        int r = i >> 6, j = i & 63;
        As[i] = g_Q[(size_t)(t0 + r) * DMODEL + h * HD + j];
    }
    #pragma unroll
    for (int it = 0; it < 16; it++) {
        int i = tid + it * 256;
        int dd = i >> 6, j = i & 63;
        Bt[j * 68 + dd] = Wk[(size_t)(d0 + dd) * DMODEL + h * HD + j];
    }
    __syncthreads();

    float4 acc = make_float4(0.f, 0.f, 0.f, 0.f);
    #pragma unroll
    for (int j = 0; j < 64; j++) {
        float a  = As[ty * 64 + j];
        float4 b = *reinterpret_cast<const float4*>(&Bt[j * 68 + tx * 4]);
        acc.x += a * b.x; acc.y += a * b.y;
        acc.z += a * b.z; acc.w += a * b.w;
    }
    const float s = 0.125f;
    float4 o = make_float4(acc.x * s, acc.y * s, acc.z * s, acc.w * s);
    *reinterpret_cast<float4*>(
        &g_P[((size_t)(t0 + ty) * NH + h) * DMODEL + d0 + tx * 4]) = o;
}

// ---------------- K3: per-tile attention (512 threads, dynamic smem) --------
// pool layout:
//   phase1:  Psp u64[512*4]        @ 0      (16384 B)
//            xs  float[2][16*258]  @ 16384  (2 x 16512 B)   total 49408
//   between: Lp  float[2][8][256]  @ 0      (16384 B, over dead Psp)
//   phase2:  Es2 ulonglong2[4*256] @ 16384  (16384 B, over dead xs)
//            Yp  ulonglong2[256*4] @ 32768  (16384 B, over dead xs)
#define ATTN_SMEM (16384 + 2 * 16 * 258 * 4)

__global__ __launch_bounds__(512) void attn_k(const float* __restrict__ x,
                                              const float* __restrict__ bk)
{
    extern __shared__ __align__(16) unsigned char pool[];
    u64t*       Psp = (u64t*)pool;
    float*      Lp  = (float*)pool;
    ulonglong2* Es2 = (ulonglong2*)(pool + 16384);
    ulonglong2* Yp  = (ulonglong2*)(pool + 32768);
    __shared__ float red[16];

    int tid  = threadIdx.x;
    int half = tid >> 8;          // 0/1: d-half (p1), token-half (p2)
    int t8   = tid & 255;         // token (p1), column pair (p2)
    int t = blockIdx.x;
    const float* xt = x + (size_t)t * NTOK * DMODEL;

    // stage P pre-packed as f32x2 head-pairs (coalesced on d)
    const float* Pt = g_P + (size_t)t * NH * DMODEL;
    #pragma unroll
    for (int it = 0; it < 4; it++) {
        int i = tid + it * 512;
        int d = i & 511, pp = i >> 9;
        float lo = Pt[(size_t)(2 * pp)     * DMODEL + d];
        float hi = Pt[(size_t)(2 * pp + 1) * DMODEL + d];
        Psp[d * 4 + pp] = pack2(lo, hi);
    }
    // c[h] = 0.125 * q_h . bk_h  (warps 0-7, one per head)
    if (tid < 256) {
        int h = tid >> 5, j = tid & 31;
        const float* Qt  = g_Q + (size_t)t * DMODEL + h * HD;
        const float* bkh = bk + h * HD;
        float p = Qt[j] * bkh[j] + Qt[j + 32] * bkh[j + 32];
        #pragma unroll
        for (int o = 16; o > 0; o >>= 1) p += __shfl_down_sync(0xffffffffu, p, o);
        if (j == 0) red[h] = 0.125f * p;
    }
    __syncthreads();

    // ---- phase 1: token = t8, d-range = half*256..+256 (16 chunks of 16)
    u64t la[4];
    #pragma unroll
    for (int pp = 0; pp < 4; pp++)
        la[pp] = half ? 0ull : pack2(red[2 * pp], red[2 * pp + 1]);

    float* xsh  = (float*)(pool + 16384) + half * 4128;   // [16][258]
    int dbase = half * 256;
    int srow = t8 >> 2, sf4 = t8 & 3;
    const float4* xt4 = (const float4*)xt;
    int fidx = (dbase >> 2) + sf4;
    float4 v0 = xt4[(size_t)(srow      ) * 128 + fidx];
    float4 v1 = xt4[(size_t)(srow +  64) * 128 + fidx];
    float4 v2 = xt4[(size_t)(srow + 128) * 128 + fidx];
    float4 v3 = xt4[(size_t)(srow + 192) * 128 + fidx];

    for (int c0 = 0; c0 < 256; c0 += 16) {
        int dl0 = sf4 * 4;
        #pragma unroll
        for (int k = 0; k < 4; k++) {
            float vv0 = (k==0)?v0.x:(k==1)?v0.y:(k==2)?v0.z:v0.w;
            float vv1 = (k==0)?v1.x:(k==1)?v1.y:(k==2)?v1.z:v1.w;
            float vv2 = (k==0)?v2.x:(k==1)?v2.y:(k==2)?v2.z:v2.w;
            float vv3 = (k==0)?v3.x:(k==1)?v3.y:(k==2)?v3.z:v3.w;
            xsh[(dl0 + k) * 258 + srow      ] = vv0;
            xsh[(dl0 + k) * 258 + srow +  64] = vv1;
            xsh[(dl0 + k) * 258 + srow + 128] = vv2;
            xsh[(dl0 + k) * 258 + srow + 192] = vv3;
        }
        __syncthreads();
        if (c0 + 16 < 256) {      // prefetch next chunk; hides under FMA2 block
            int f = ((dbase + c0 + 16) >> 2) + sf4;
            v0 = xt4[(size_t)(srow      ) * 128 + f];
            v1 = xt4[(size_t)(srow +  64) * 128 + f];
            v2 = xt4[(size_t)(srow + 128) * 128 + f];
            v3 = xt4[(size_t)(srow + 192) * 128 + f];
        }
        #pragma unroll
        for (int dl = 0; dl < 16; dl++) {
            float xv = xsh[dl * 258 + t8];                 // conflict-free
            u64t xd = pack2(xv, xv);
            const ulonglong2* Pp =
                (const ulonglong2*)&Psp[(dbase + c0 + dl) * 4];
            ulonglong2 p0 = Pp[0], p1 = Pp[1];             // broadcast LDS.128
            fma2(la[0], xd, p0.x); fma2(la[1], xd, p0.y);
            fma2(la[2], xd, p1.x); fma2(la[3], xd, p1.y);
        }
        __syncthreads();
    }
    // write partial logits: Lp[half][h][n]   (Psp dead after last sync)
    #pragma unroll
    for (int pp = 0; pp < 4; pp++) {
        float2 f = unpack2(la[pp]);
        Lp[half * 2048 + (2 * pp)     * 256 + t8] = f.x;
        Lp[half * 2048 + (2 * pp + 1) * 256 + t8] = f.y;
    }
    __syncthreads();

    // ---- softmax
    int wid = tid >> 5, lane = tid & 31;
    if (wid < 8) {   // combine halves + max (warp per head)
        float m = -1e30f;
        for (int i = lane; i < 256; i += 32) {
            float v = Lp[wid * 256 + i] + Lp[2048 + wid * 256 + i];
            Lp[wid * 256 + i] = v;
            m = fmaxf(m, v);
        }
        #pragma unroll
        for (int o = 16; o > 0; o >>= 1)
            m = fmaxf(m, __shfl_xor_sync(0xffffffffu, m, o));
        if (lane == 0) red[wid] = m;
    }
    __syncthreads();
    {   // exp: half0 -> head-pairs 0,1 ; half1 -> 2,3
        #pragma unroll
        for (int jj = 0; jj < 2; jj++) {
            int j = half * 2 + jj;
            float e0 = __expf(Lp[(2 * j)     * 256 + t8] - red[2 * j]);
            float e1 = __expf(Lp[(2 * j + 1) * 256 + t8] - red[2 * j + 1]);
            ulonglong2 v; v.x = pack2(e0, e0); v.y = pack2(e1, e1);
            Es2[j * 256 + t8] = v;
        }
    }
    __syncthreads();
    if (wid < 8) {   // sum per head -> 1/s
        int j = wid >> 1, hi = wid & 1;
        float s = 0.f;
        for (int i = lane; i < 256; i += 32) {
            ulonglong2 v = Es2[j * 256 + i];
            s += unpack2(hi ? v.y : v.x).x;
        }
        #pragma unroll
        for (int o = 16; o > 0; o >>= 1) s += __shfl_xor_sync(0xffffffffu, s, o);
        if (lane == 0) red[8 + wid] = 1.0f / s;
    }
    __syncthreads();

    // ---- phase 2: col pair = t8, tokens half*128..+128
    u64t acc[8];
    #pragma unroll
    for (int h = 0; h < 8; h++) acc[h] = 0ull;
    const float2* x2 = (const float2*)xt + t8;
    int tok0 = half * 128;
    #pragma unroll 8
    for (int nn = 0; nn < 128; nn++) {
        float2 xv = x2[(size_t)(tok0 + nn) * 256];     // coalesced, L2-hit
        u64t xp = pack2(xv.x, xv.y);
        ulonglong2 e0 = Es2[0 * 256 + tok0 + nn];      // broadcast LDS.128
        ulonglong2 e1 = Es2[1 * 256 + tok0 + nn];
        ulonglong2 e2 = Es2[2 * 256 + tok0 + nn];
        ulonglong2 e3 = Es2[3 * 256 + tok0 + nn];
        fma2(acc[0], e0.x, xp); fma2(acc[1], e0.y, xp);
        fma2(acc[2], e1.x, xp); fma2(acc[3], e1.y, xp);
        fma2(acc[4], e2.x, xp); fma2(acc[5], e2.y, xp);
        fma2(acc[6], e3.x, xp); fma2(acc[7], e3.y, xp);
    }
    if (half == 1) {   // export partials
        #pragma unroll
        for (int k = 0; k < 4; k++) {
            ulonglong2 v; v.x = acc[2 * k]; v.y = acc[2 * k + 1];
            Yp[t8 * 4 + k] = v;
        }
    }
    __syncthreads();
    if (half == 0) {   // combine + scale + write
        #pragma unroll
        for (int k = 0; k < 4; k++) {
            ulonglong2 v = Yp[t8 * 4 + k];
            float2 a0 = unpack2(acc[2 * k]),     b0 = unpack2(v.x);
            float2 a1 = unpack2(acc[2 * k + 1]), b1 = unpack2(v.y);
            float i0 = red[8 + 2 * k], i1 = red[8 + 2 * k + 1];
            float2 o0; o0.x = (a0.x + b0.x) * i0; o0.y = (a0.y + b0.y) * i0;
            float2 o1; o1.x = (a1.x + b1.x) * i1; o1.y = (a1.y + b1.y) * i1;
            ((float2*)(g_Y + ((size_t)t * NH + 2 * k)     * DMODEL))[t8] = o0;
            ((float2*)(g_Y + ((size_t)t * NH + 2 * k + 1) * DMODEL))[t8] = o1;
        }
    }
}

// ---------------------------------------------------------------------------
extern "C" void kernel_launch(void* const* d_in, const int* in_sizes, int n_in,
                              void* d_out, int out_size)
{
    const float* x  = (const float*)d_in[0];
    const float* Wq = (const float*)d_in[1];
    const float* bq = (const float*)d_in[2];
    const float* Wk = (const float*)d_in[3];
    const float* bk = (const float*)d_in[4];
    const float* Wv = (const float*)d_in[5];
    const float* bv = (const float*)d_in[6];
    const float* Wo = (const float*)d_in[7];
    const float* bo = (const float*)d_in[8];
    float* out = (float*)d_out;
    (void)in_sizes; (void)n_in; (void)out_size;

    void *pQ, *pY, *pC;
    cudaGetSymbolAddress(&pQ, g_Q);
    cudaGetSymbolAddress(&pY, g_Y);
    cudaGetSymbolAddress(&pC, g_ctx);

    cudaFuncSetAttribute(attn_k, cudaFuncAttributeMaxDynamicSharedMemorySize,
                         ATTN_SMEM);

    // mine #0: K1: Q = X0 @ Wq + bq
    gemm_k<<<dim3(8, 8, 1), 256>>>(
        x, (size_t)(NTOK * DMODEL), 0,
        Wq, DMODEL, 0, bq, 0,
        (float*)pQ, DMODEL, 0, DMODEL);

    // mine #1, #2: K2 split 4+4 heads, 512 CTAs each
    pproj_k<<<dim3(16, 8, 4), 256>>>(Wk, 0);
    pproj_k<<<dim3(16, 8, 4), 256>>>(Wk, 4);

    // mine #3: K3: per-tile attention -> g_Y   (profiled launch)
    attn_k<<<TT, 512, ATTN_SMEM>>>(x, bk);

    // mine #4: K4: ctx_h = Y_h @ Wv[:,h] + bv_h
    gemm_k<<<dim3(8, 1, NH), 256>>>(
        (const float*)pY, (size_t)(NH * DMODEL), (size_t)DMODEL,
        Wv, DMODEL, HD, bv, HD,
        (float*)pC, DMODEL, HD, DMODEL);

    // mine #5: K5: out = ctx @ Wo + bo
    gemm_k<<<dim3(8, 8, 1), 256>>>(
        (const float*)pC, (size_t)DMODEL, 0,
        Wo, DMODEL, 0, bo, 0,
        out, DMODEL, 0, DMODEL);
}

// round 16
// speedup vs baseline: 1.5221x; 1.0119x over previous
#include <cuda_runtime.h>
#include <math.h>

#define TT     256   // B*S tiles
#define NTOK   256   // N tokens per tile
#define DMODEL 512
#define NH     8
#define HD     64

typedef unsigned long long u64t;

// ---------------- f32x2 packed-math helpers (B300 FFMA2 path) ---------------
__device__ __forceinline__ u64t pack2(float lo, float hi) {
    u64t r; asm("mov.b64 %0, {%1,%2};" : "=l"(r) : "f"(lo), "f"(hi)); return r;
}
__device__ __forceinline__ void fma2(u64t& d, u64t a, u64t b) {
    asm("fma.rn.f32x2 %0, %1, %2, %0;" : "+l"(d) : "l"(a), "l"(b));
}
__device__ __forceinline__ float2 unpack2(u64t v) {
    float2 f; asm("mov.b64 {%0,%1}, %2;" : "=f"(f.x), "=f"(f.y) : "l"(v)); return f;
}

// ---------------- scratch (device globals: no allocation allowed) -----------
__device__ float g_Q[TT * DMODEL];          // q per tile (with bias)
__device__ float g_P[TT * NH * DMODEL];     // [t][h][d], pre-scaled by 1/8
__device__ float g_Y[TT * NH * DMODEL];     // [t][h][d], softmax-weighted x sums
__device__ float g_ctx[TT * DMODEL];        // concat heads per tile

// ------------- register-blocked GEMM: C = A @ B + bias ----------------------
__global__ __launch_bounds__(256) void gemm_k(
    const float* __restrict__ A, size_t a_stride, size_t a_zoff,
    const float* __restrict__ B, int b_stride, int b_zoff,
    const float* __restrict__ bias, int bias_zoff,
    float* __restrict__ C, int c_stride, int c_zoff,
    int Kdim)
{
    __shared__ __align__(16) u64t  Atp[2][32 * 34];
    __shared__ __align__(16) float Bs[2][32 * 64];
    int tid = threadIdx.x;
    int tx = tid & 15, ty = tid >> 4;
    int t0 = blockIdx.x * 32;
    int n0 = blockIdx.y * 64;
    int z  = blockIdx.z;

    const float* Ab    = A + (size_t)z * a_zoff;
    const float* Bb    = B + (size_t)z * b_zoff + n0;
    const float* biasb = bias + (size_t)z * bias_zoff + n0;
    float*       Cb    = C + (size_t)z * c_zoff + n0;

    int arow = tid >> 3, akq = tid & 7;
    const float* Aptr = Ab + (size_t)(t0 + arow) * a_stride + akq * 4;
    int br0 = tid >> 4, bc0 = (tid & 15) * 4;
    const float* Bptr = Bb + (size_t)br0 * b_stride + bc0;

    float4 pa, pb0, pb1;
    pa  = *(const float4*)(Aptr);
    pb0 = *(const float4*)(Bptr);
    pb1 = *(const float4*)(Bptr + (size_t)16 * b_stride);
    Atp[0][(akq * 4 + 0) * 34 + arow] = pack2(pa.x, pa.x);
    Atp[0][(akq * 4 + 1) * 34 + arow] = pack2(pa.y, pa.y);
    Atp[0][(akq * 4 + 2) * 34 + arow] = pack2(pa.z, pa.z);
    Atp[0][(akq * 4 + 3) * 34 + arow] = pack2(pa.w, pa.w);
    *(float4*)&Bs[0][br0 * 64 + bc0]        = pb0;
    *(float4*)&Bs[0][(br0 + 16) * 64 + bc0] = pb1;
    __syncthreads();

    u64t a00 = 0ull, a01 = 0ull, a10 = 0ull, a11 = 0ull;
    int nch = Kdim >> 5;
    for (int c = 0; c < nch; c++) {
        int cur = c & 1;
        if (c + 1 < nch) {
            const float* Ap = Aptr + (c + 1) * 32;
            const float* Bp = Bptr + (size_t)(c + 1) * 32 * b_stride;
            pa  = *(const float4*)(Ap);
            pb0 = *(const float4*)(Bp);
            pb1 = *(const float4*)(Bp + (size_t)16 * b_stride);
        }
        const u64t*  Ar = &Atp[cur][ty * 2];
        const float* Br = &Bs[cur][tx * 4];
        #pragma unroll
        for (int kk = 0; kk < 32; kk++) {
            ulonglong2 av = *(const ulonglong2*)&Ar[kk * 34];
            ulonglong2 bv = *(const ulonglong2*)&Br[kk * 64];
            fma2(a00, av.x, bv.x); fma2(a01, av.x, bv.y);
            fma2(a10, av.y, bv.x); fma2(a11, av.y, bv.y);
        }
        if (c + 1 < nch) {
            int nxt = cur ^ 1;
            Atp[nxt][(akq * 4 + 0) * 34 + arow] = pack2(pa.x, pa.x);
            Atp[nxt][(akq * 4 + 1) * 34 + arow] = pack2(pa.y, pa.y);
            Atp[nxt][(akq * 4 + 2) * 34 + arow] = pack2(pa.z, pa.z);
            Atp[nxt][(akq * 4 + 3) * 34 + arow] = pack2(pa.w, pa.w);
            *(float4*)&Bs[nxt][br0 * 64 + bc0]        = pb0;
            *(float4*)&Bs[nxt][(br0 + 16) * 64 + bc0] = pb1;
        }
        __syncthreads();
    }
    float4 bb = *(const float4*)&biasb[tx * 4];
    float2 r00 = unpack2(a00), r01 = unpack2(a01);
    float2 r10 = unpack2(a10), r11 = unpack2(a11);
    float4 o0 = make_float4(r00.x + bb.x, r00.y + bb.y, r01.x + bb.z, r01.y + bb.w);
    float4 o1 = make_float4(r10.x + bb.x, r10.y + bb.y, r11.x + bb.z, r11.y + bb.w);
    *(float4*)&Cb[(size_t)(t0 + ty * 2)     * c_stride + tx * 4] = o0;
    *(float4*)&Cb[(size_t)(t0 + ty * 2 + 1) * c_stride + tx * 4] = o1;
}

// ---- K2: P[t,h,d] = 0.125 * sum_j Q[t,h*64+j] * Wk[d, h*64+j] --------------
__global__ __launch_bounds__(256) void pproj_k(const float* __restrict__ Wk)
{
    __shared__ float As[16 * 64];
    __shared__ float Bt[64 * 68];
    int tid = threadIdx.x;
    int tx = tid & 15, ty = tid >> 4;
    int t0 = blockIdx.x * 16;
    int d0 = blockIdx.y * 64;
    int h  = blockIdx.z;

    #pragma unroll
    for (int it = 0; it < 4; it++) {
        int i = tid + it * 256;
        int r = i >> 6, j = i & 63;
        As[i] = g_Q[(size_t)(t0 + r) * DMODEL + h * HD + j];
    }
    #pragma unroll
    for (int it = 0; it < 16; it++) {
        int i = tid + it * 256;
        int dd = i >> 6, j = i & 63;
        Bt[j * 68 + dd] = Wk[(size_t)(d0 + dd) * DMODEL + h * HD + j];
    }
    __syncthreads();

    float4 acc = make_float4(0.f, 0.f, 0.f, 0.f);
    #pragma unroll
    for (int j = 0; j < 64; j++) {
        float a  = As[ty * 64 + j];
        float4 b = *reinterpret_cast<const float4*>(&Bt[j * 68 + tx * 4]);
        acc.x += a * b.x; acc.y += a * b.y;
        acc.z += a * b.z; acc.w += a * b.w;
    }
    const float s = 0.125f;
    float4 o = make_float4(acc.x * s, acc.y * s, acc.z * s, acc.w * s);
    *reinterpret_cast<float4*>(
        &g_P[((size_t)(t0 + ty) * NH + h) * DMODEL + d0 + tx * 4]) = o;
}

// ---------------- K3: per-tile attention (512 threads, dynamic smem) --------
// pool layout:
//   phase1:  Psp u64[512*4]        @ 0      (16384 B)
//            xs  float[2][16*258]  @ 16384  (2 x 16512 B)   total 49408
//   between: Lp  float[2][8][256]  @ 0      (16384 B, over dead Psp)
//   phase2:  Es2 ulonglong2[4*256] @ 16384  (16384 B, over dead xs)
//            Yp  ulonglong2[256*4] @ 32768  (16384 B, over dead xs)
#define ATTN_SMEM (16384 + 2 * 16 * 258 * 4)

__global__ __launch_bounds__(512) void attn_k(const float* __restrict__ x,
                                              const float* __restrict__ bk)
{
    extern __shared__ __align__(16) unsigned char pool[];
    u64t*       Psp = (u64t*)pool;
    float*      Lp  = (float*)pool;
    ulonglong2* Es2 = (ulonglong2*)(pool + 16384);
    ulonglong2* Yp  = (ulonglong2*)(pool + 32768);
    __shared__ float red[16];

    int tid  = threadIdx.x;
    int half = tid >> 8;          // phase 1: d-half
    int t8   = tid & 255;         // phase 1: token
    int t = blockIdx.x;
    const float* xt = x + (size_t)t * NTOK * DMODEL;

    // stage P pre-packed as f32x2 head-pairs (coalesced on d)
    const float* Pt = g_P + (size_t)t * NH * DMODEL;
    #pragma unroll
    for (int it = 0; it < 4; it++) {
        int i = tid + it * 512;
        int d = i & 511, pp = i >> 9;
        float lo = Pt[(size_t)(2 * pp)     * DMODEL + d];
        float hi = Pt[(size_t)(2 * pp + 1) * DMODEL + d];
        Psp[d * 4 + pp] = pack2(lo, hi);
    }
    // c[h] = 0.125 * q_h . bk_h  (warps 0-7, one per head)
    if (tid < 256) {
        int h = tid >> 5, j = tid & 31;
        const float* Qt  = g_Q + (size_t)t * DMODEL + h * HD;
        const float* bkh = bk + h * HD;
        float p = Qt[j] * bkh[j] + Qt[j + 32] * bkh[j + 32];
        #pragma unroll
        for (int o = 16; o > 0; o >>= 1) p += __shfl_down_sync(0xffffffffu, p, o);
        if (j == 0) red[h] = 0.125f * p;
    }
    __syncthreads();

    // ---- phase 1: token = t8, d-range = half*256..+256 (16 chunks of 16)
    u64t la[4];
    #pragma unroll
    for (int pp = 0; pp < 4; pp++)
        la[pp] = half ? 0ull : pack2(red[2 * pp], red[2 * pp + 1]);

    float* xsh  = (float*)(pool + 16384) + half * 4128;   // [16][258]
    int dbase = half * 256;
    int srow = t8 >> 2, sf4 = t8 & 3;
    const float4* xt4 = (const float4*)xt;
    int fidx = (dbase >> 2) + sf4;
    float4 v0 = xt4[(size_t)(srow      ) * 128 + fidx];
    float4 v1 = xt4[(size_t)(srow +  64) * 128 + fidx];
    float4 v2 = xt4[(size_t)(srow + 128) * 128 + fidx];
    float4 v3 = xt4[(size_t)(srow + 192) * 128 + fidx];

    for (int c0 = 0; c0 < 256; c0 += 16) {
        int dl0 = sf4 * 4;
        #pragma unroll
        for (int k = 0; k < 4; k++) {
            float vv0 = (k==0)?v0.x:(k==1)?v0.y:(k==2)?v0.z:v0.w;
            float vv1 = (k==0)?v1.x:(k==1)?v1.y:(k==2)?v1.z:v1.w;
            float vv2 = (k==0)?v2.x:(k==1)?v2.y:(k==2)?v2.z:v2.w;
            float vv3 = (k==0)?v3.x:(k==1)?v3.y:(k==2)?v3.z:v3.w;
            xsh[(dl0 + k) * 258 + srow      ] = vv0;
            xsh[(dl0 + k) * 258 + srow +  64] = vv1;
            xsh[(dl0 + k) * 258 + srow + 128] = vv2;
            xsh[(dl0 + k) * 258 + srow + 192] = vv3;
        }
        __syncthreads();
        if (c0 + 16 < 256) {      // prefetch next chunk; hides under FMA2 block
            int f = ((dbase + c0 + 16) >> 2) + sf4;
            v0 = xt4[(size_t)(srow      ) * 128 + f];
            v1 = xt4[(size_t)(srow +  64) * 128 + f];
            v2 = xt4[(size_t)(srow + 128) * 128 + f];
            v3 = xt4[(size_t)(srow + 192) * 128 + f];
        }
        #pragma unroll
        for (int dl = 0; dl < 16; dl++) {
            float xv = xsh[dl * 258 + t8];                 // conflict-free
            u64t xd = pack2(xv, xv);
            const ulonglong2* Pp =
                (const ulonglong2*)&Psp[(dbase + c0 + dl) * 4];
            ulonglong2 p0 = Pp[0], p1 = Pp[1];             // broadcast LDS.128
            fma2(la[0], xd, p0.x); fma2(la[1], xd, p0.y);
            fma2(la[2], xd, p1.x); fma2(la[3], xd, p1.y);
        }
        __syncthreads();
    }
    // write partial logits: Lp[half][h][n]   (Psp dead after last sync)
    #pragma unroll
    for (int pp = 0; pp < 4; pp++) {
        float2 f = unpack2(la[pp]);
        Lp[half * 2048 + (2 * pp)     * 256 + t8] = f.x;
        Lp[half * 2048 + (2 * pp + 1) * 256 + t8] = f.y;
    }
    __syncthreads();

    // ---- softmax
    int wid = tid >> 5, lane = tid & 31;
    if (wid < 8) {   // combine halves + max (warp per head)
        float m = -1e30f;
        for (int i = lane; i < 256; i += 32) {
            float v = Lp[wid * 256 + i] + Lp[2048 + wid * 256 + i];
            Lp[wid * 256 + i] = v;
            m = fmaxf(m, v);
        }
        #pragma unroll
        for (int o = 16; o > 0; o >>= 1)
            m = fmaxf(m, __shfl_xor_sync(0xffffffffu, m, o));
        if (lane == 0) red[wid] = m;
    }
    __syncthreads();
    {   // exp: half0 -> head-pairs 0,1 ; half1 -> 2,3
        #pragma unroll
        for (int jj = 0; jj < 2; jj++) {
            int j = half * 2 + jj;
            float e0 = __expf(Lp[(2 * j)     * 256 + t8] - red[2 * j]);
            float e1 = __expf(Lp[(2 * j + 1) * 256 + t8] - red[2 * j + 1]);
            ulonglong2 v; v.x = pack2(e0, e0); v.y = pack2(e1, e1);
            Es2[j * 256 + t8] = v;
        }
    }
    __syncthreads();
    if (wid < 8) {   // sum per head -> 1/s
        int j = wid >> 1, hi = wid & 1;
        float s = 0.f;
        for (int i = lane; i < 256; i += 32) {
            ulonglong2 v = Es2[j * 256 + i];
            s += unpack2(hi ? v.y : v.x).x;
        }
        #pragma unroll
        for (int o = 16; o > 0; o >>= 1) s += __shfl_xor_sync(0xffffffffu, s, o);
        if (lane == 0) red[8 + wid] = 1.0f / s;
    }
    __syncthreads();

    // ---- phase 2: thread = (f4-column, head-half, token-half)
    // per token: 1 LDG.128 (x, as packed u64 pairs) + 2 LDS.128 (e for 4
    // heads) + 8 FMA2  -> 40% fewer LSU ops than col-pair layout.
    int f4c = tid & 127;          // float4 column (cols 4*f4c .. +3)
    int hh  = (tid >> 7) & 1;     // head-half: heads 4*hh .. +3
    int th  = tid >> 8;           // token-half
    u64t acc[8];
    #pragma unroll
    for (int k = 0; k < 8; k++) acc[k] = 0ull;

    const ulonglong2* x4u = (const ulonglong2*)xt + f4c;   // row stride 128
    const ulonglong2* Ep0 = &Es2[(2 * hh)     * 256];
    const ulonglong2* Ep1 = &Es2[(2 * hh + 1) * 256];
    int tok0 = th * 128;
    #pragma unroll 8
    for (int nn = 0; nn < 128; nn++) {
        int tok = tok0 + nn;
        ulonglong2 xv = x4u[(size_t)tok * 128];    // coalesced LDG.128
        ulonglong2 e0 = Ep0[tok];                  // broadcast LDS.128
        ulonglong2 e1 = Ep1[tok];
        fma2(acc[0], e0.x, xv.x); fma2(acc[1], e0.x, xv.y);   // head 4hh
        fma2(acc[2], e0.y, xv.x); fma2(acc[3], e0.y, xv.y);   // head 4hh+1
        fma2(acc[4], e1.x, xv.x); fma2(acc[5], e1.x, xv.y);   // head 4hh+2
        fma2(acc[6], e1.y, xv.x); fma2(acc[7], e1.y, xv.y);   // head 4hh+3
    }
    if (th == 1) {   // export partials: Yp[(hh*128+f4c)*4 + k]
        #pragma unroll
        for (int k = 0; k < 4; k++) {
            ulonglong2 v; v.x = acc[2 * k]; v.y = acc[2 * k + 1];
            Yp[(hh * 128 + f4c) * 4 + k] = v;
        }
    }
    __syncthreads();
    if (th == 0) {   // combine + scale + write float4 per head
        #pragma unroll
        for (int k = 0; k < 4; k++) {
            int h = 4 * hh + k;
            ulonglong2 v = Yp[(hh * 128 + f4c) * 4 + k];
            float2 a0 = unpack2(acc[2 * k]),     b0 = unpack2(v.x);
            float2 a1 = unpack2(acc[2 * k + 1]), b1 = unpack2(v.y);
            float inv = red[8 + h];
            float4 o;
            o.x = (a0.x + b0.x) * inv; o.y = (a0.y + b0.y) * inv;
            o.z = (a1.x + b1.x) * inv; o.w = (a1.y + b1.y) * inv;
            ((float4*)(g_Y + ((size_t)t * NH + h) * DMODEL))[f4c] = o;
        }
    }
}

// ---------------------------------------------------------------------------
extern "C" void kernel_launch(void* const* d_in, const int* in_sizes, int n_in,
                              void* d_out, int out_size)
{
    const float* x  = (const float*)d_in[0];
    const float* Wq = (const float*)d_in[1];
    const float* bq = (const float*)d_in[2];
    const float* Wk = (const float*)d_in[3];
    const float* bk = (const float*)d_in[4];
    const float* Wv = (const float*)d_in[5];
    const float* bv = (const float*)d_in[6];
    const float* Wo = (const float*)d_in[7];
    const float* bo = (const float*)d_in[8];
    float* out = (float*)d_out;
    (void)in_sizes; (void)n_in; (void)out_size;

    void *pQ, *pY, *pC;
    cudaGetSymbolAddress(&pQ, g_Q);
    cudaGetSymbolAddress(&pY, g_Y);
    cudaGetSymbolAddress(&pC, g_ctx);

    cudaFuncSetAttribute(attn_k, cudaFuncAttributeMaxDynamicSharedMemorySize,
                         ATTN_SMEM);

    // mine #0: K1: Q = X0 @ Wq + bq
    gemm_k<<<dim3(8, 8, 1), 256>>>(
        x, (size_t)(NTOK * DMODEL), 0,
        Wq, DMODEL, 0, bq, 0,
        (float*)pQ, DMODEL, 0, DMODEL);

    // mine #1: K2: all 8 heads in one launch (1024 CTAs)
    pproj_k<<<dim3(16, 8, NH), 256>>>(Wk);

    // mine #2: K3: per-tile attention -> g_Y
    attn_k<<<TT, 512, ATTN_SMEM>>>(x, bk);

    // mine #3: K4: ctx_h = Y_h @ Wv[:,h] + bv_h   (PROFILED this round)
    gemm_k<<<dim3(8, 1, NH), 256>>>(
        (const float*)pY, (size_t)(NH * DMODEL), (size_t)DMODEL,
        Wv, DMODEL, HD, bv, HD,
        (float*)pC, DMODEL, HD, DMODEL);

    // mine #4: K5: out = ctx @ Wo + bo
    gemm_k<<<dim3(8, 8, 1), 256>>>(
        (const float*)pC, (size_t)DMODEL, 0,
        Wo, DMODEL, 0, bo, 0,
        out, DMODEL, 0, DMODEL);
}

// round 17
// speedup vs baseline: 1.8386x; 1.2080x over previous
#include <cuda_runtime.h>
#include <math.h>

#define TT     256   // B*S tiles
#define NTOK   256   // N tokens per tile
#define DMODEL 512
#define NH     8
#define HD     64

typedef unsigned long long u64t;

// ---------------- f32x2 packed-math helpers (B300 FFMA2 path) ---------------
__device__ __forceinline__ u64t pack2(float lo, float hi) {
    u64t r; asm("mov.b64 %0, {%1,%2};" : "=l"(r) : "f"(lo), "f"(hi)); return r;
}
__device__ __forceinline__ void fma2(u64t& d, u64t a, u64t b) {
    asm("fma.rn.f32x2 %0, %1, %2, %0;" : "+l"(d) : "l"(a), "l"(b));
}
__device__ __forceinline__ float2 unpack2(u64t v) {
    float2 f; asm("mov.b64 {%0,%1}, %2;" : "=f"(f.x), "=f"(f.y) : "l"(v)); return f;
}

// ---------------- scratch (device globals: no allocation allowed) -----------
__device__ float g_Q[TT * DMODEL];          // q per tile (with bias)
__device__ float g_P[TT * NH * DMODEL];     // [t][h][d], pre-scaled by 1/8
__device__ float g_Y[TT * NH * DMODEL];     // [t][h][d], softmax-weighted x sums
__device__ float g_ctx[TT * DMODEL];        // concat heads per tile

// ---------------- zero destinations for split-K atomics ---------------------
__global__ __launch_bounds__(256) void zero_k(float* __restrict__ a,
                                              float* __restrict__ b,
                                              float* __restrict__ c)
{
    int i = blockIdx.x * 256 + threadIdx.x;          // 32768 float4 per buffer
    float4 z = make_float4(0.f, 0.f, 0.f, 0.f);
    ((float4*)a)[i] = z;
    ((float4*)b)[i] = z;
    ((float4*)c)[i] = z;
}

// ------------- split-K register-blocked GEMM: C += A @ B (+ bias on ks==0) --
// 32x64 tile, 256 threads, 2x4 micro-tile. K split 4 ways (128 each);
// partials land via atomicAdd. blockIdx.z = ks * nzz + z.
__global__ __launch_bounds__(256) void gemm_k(
    const float* __restrict__ A, size_t a_stride, size_t a_zoff,
    const float* __restrict__ B, int b_stride, int b_zoff,
    const float* __restrict__ bias, int bias_zoff,
    float* __restrict__ C, int c_stride, int c_zoff,
    int nzz)
{
    __shared__ __align__(16) u64t  Atp[2][32 * 34];
    __shared__ __align__(16) float Bs[2][32 * 64];
    int tid = threadIdx.x;
    int tx = tid & 15, ty = tid >> 4;
    int t0 = blockIdx.x * 32;
    int n0 = blockIdx.y * 64;
    int z  = blockIdx.z % nzz;
    int ks = blockIdx.z / nzz;                       // k-slice 0..3
    int k0s = ks * 128;

    const float* Ab    = A + (size_t)z * a_zoff + k0s;
    const float* Bb    = B + (size_t)z * b_zoff + (size_t)k0s * b_stride + n0;
    const float* biasb = bias + (size_t)z * bias_zoff + n0;
    float*       Cb    = C + (size_t)z * c_zoff + n0;

    int arow = tid >> 3, akq = tid & 7;
    const float* Aptr = Ab + (size_t)(t0 + arow) * a_stride + akq * 4;
    int br0 = tid >> 4, bc0 = (tid & 15) * 4;
    const float* Bptr = Bb + (size_t)br0 * b_stride + bc0;

    float4 pa, pb0, pb1;
    pa  = *(const float4*)(Aptr);
    pb0 = *(const float4*)(Bptr);
    pb1 = *(const float4*)(Bptr + (size_t)16 * b_stride);
    Atp[0][(akq * 4 + 0) * 34 + arow] = pack2(pa.x, pa.x);
    Atp[0][(akq * 4 + 1) * 34 + arow] = pack2(pa.y, pa.y);
    Atp[0][(akq * 4 + 2) * 34 + arow] = pack2(pa.z, pa.z);
    Atp[0][(akq * 4 + 3) * 34 + arow] = pack2(pa.w, pa.w);
    *(float4*)&Bs[0][br0 * 64 + bc0]        = pb0;
    *(float4*)&Bs[0][(br0 + 16) * 64 + bc0] = pb1;
    __syncthreads();

    u64t a00 = 0ull, a01 = 0ull, a10 = 0ull, a11 = 0ull;
    const int nch = 4;                               // 128 k per slice
    for (int c = 0; c < nch; c++) {
        int cur = c & 1;
        if (c + 1 < nch) {
            const float* Ap = Aptr + (c + 1) * 32;
            const float* Bp = Bptr + (size_t)(c + 1) * 32 * b_stride;
            pa  = *(const float4*)(Ap);
            pb0 = *(const float4*)(Bp);
            pb1 = *(const float4*)(Bp + (size_t)16 * b_stride);
        }
        const u64t*  Ar = &Atp[cur][ty * 2];
        const float* Br = &Bs[cur][tx * 4];
        #pragma unroll
        for (int kk = 0; kk < 32; kk++) {
            ulonglong2 av = *(const ulonglong2*)&Ar[kk * 34];
            ulonglong2 bv = *(const ulonglong2*)&Br[kk * 64];
            fma2(a00, av.x, bv.x); fma2(a01, av.x, bv.y);
            fma2(a10, av.y, bv.x); fma2(a11, av.y, bv.y);
        }
        if (c + 1 < nch) {
            int nxt = cur ^ 1;
            Atp[nxt][(akq * 4 + 0) * 34 + arow] = pack2(pa.x, pa.x);
            Atp[nxt][(akq * 4 + 1) * 34 + arow] = pack2(pa.y, pa.y);
            Atp[nxt][(akq * 4 + 2) * 34 + arow] = pack2(pa.z, pa.z);
            Atp[nxt][(akq * 4 + 3) * 34 + arow] = pack2(pa.w, pa.w);
            *(float4*)&Bs[nxt][br0 * 64 + bc0]        = pb0;
            *(float4*)&Bs[nxt][(br0 + 16) * 64 + bc0] = pb1;
        }
        __syncthreads();
    }
    float2 r00 = unpack2(a00), r01 = unpack2(a01);
    float2 r10 = unpack2(a10), r11 = unpack2(a11);
    float v0[4] = {r00.x, r00.y, r01.x, r01.y};
    float v1[4] = {r10.x, r10.y, r11.x, r11.y};
    if (ks == 0) {   // fold bias into slice 0 (atomicAdd is commutative)
        float4 bb = *(const float4*)&biasb[tx * 4];
        v0[0] += bb.x; v0[1] += bb.y; v0[2] += bb.z; v0[3] += bb.w;
        v1[0] += bb.x; v1[1] += bb.y; v1[2] += bb.z; v1[3] += bb.w;
    }
    float* c0 = &Cb[(size_t)(t0 + ty * 2)     * c_stride + tx * 4];
    float* c1 = &Cb[(size_t)(t0 + ty * 2 + 1) * c_stride + tx * 4];
    #pragma unroll
    for (int j = 0; j < 4; j++) {
        atomicAdd(c0 + j, v0[j]);
        atomicAdd(c1 + j, v1[j]);
    }
}

// ---- K2: P[t,h,d] = 0.125 * sum_j Q[t,h*64+j] * Wk[d, h*64+j] --------------
__global__ __launch_bounds__(256) void pproj_k(const float* __restrict__ Wk)
{
    __shared__ float As[16 * 64];
    __shared__ float Bt[64 * 68];
    int tid = threadIdx.x;
    int tx = tid & 15, ty = tid >> 4;
    int t0 = blockIdx.x * 16;
    int d0 = blockIdx.y * 64;
    int h  = blockIdx.z;

    #pragma unroll
    for (int it = 0; it < 4; it++) {
        int i = tid + it * 256;
        int r = i >> 6, j = i & 63;
        As[i] = g_Q[(size_t)(t0 + r) * DMODEL + h * HD + j];
    }
    #pragma unroll
    for (int it = 0; it < 16; it++) {
        int i = tid + it * 256;
        int dd = i >> 6, j = i & 63;
        Bt[j * 68 + dd] = Wk[(size_t)(d0 + dd) * DMODEL + h * HD + j];
    }
    __syncthreads();

    float4 acc = make_float4(0.f, 0.f, 0.f, 0.f);
    #pragma unroll
    for (int j = 0; j < 64; j++) {
        float a  = As[ty * 64 + j];
        float4 b = *reinterpret_cast<const float4*>(&Bt[j * 68 + tx * 4]);
        acc.x += a * b.x; acc.y += a * b.y;
        acc.z += a * b.z; acc.w += a * b.w;
    }
    const float s = 0.125f;
    float4 o = make_float4(acc.x * s, acc.y * s, acc.z * s, acc.w * s);
    *reinterpret_cast<float4*>(
        &g_P[((size_t)(t0 + ty) * NH + h) * DMODEL + d0 + tx * 4]) = o;
}

// ---------------- K3: per-tile attention (512 threads, dynamic smem) --------
#define ATTN_SMEM (16384 + 2 * 16 * 258 * 4)

__global__ __launch_bounds__(512) void attn_k(const float* __restrict__ x,
                                              const float* __restrict__ bk)
{
    extern __shared__ __align__(16) unsigned char pool[];
    u64t*       Psp = (u64t*)pool;
    float*      Lp  = (float*)pool;
    ulonglong2* Es2 = (ulonglong2*)(pool + 16384);
    ulonglong2* Yp  = (ulonglong2*)(pool + 32768);
    __shared__ float red[16];

    int tid  = threadIdx.x;
    int half = tid >> 8;          // phase 1: d-half
    int t8   = tid & 255;         // phase 1: token
    int t = blockIdx.x;
    const float* xt = x + (size_t)t * NTOK * DMODEL;

    const float* Pt = g_P + (size_t)t * NH * DMODEL;
    #pragma unroll
    for (int it = 0; it < 4; it++) {
        int i = tid + it * 512;
        int d = i & 511, pp = i >> 9;
        float lo = Pt[(size_t)(2 * pp)     * DMODEL + d];
        float hi = Pt[(size_t)(2 * pp + 1) * DMODEL + d];
        Psp[d * 4 + pp] = pack2(lo, hi);
    }
    if (tid < 256) {
        int h = tid >> 5, j = tid & 31;
        const float* Qt  = g_Q + (size_t)t * DMODEL + h * HD;
        const float* bkh = bk + h * HD;
        float p = Qt[j] * bkh[j] + Qt[j + 32] * bkh[j + 32];
        #pragma unroll
        for (int o = 16; o > 0; o >>= 1) p += __shfl_down_sync(0xffffffffu, p, o);
        if (j == 0) red[h] = 0.125f * p;
    }
    __syncthreads();

    // ---- phase 1: token = t8, d-range = half*256..+256
    u64t la[4];
    #pragma unroll
    for (int pp = 0; pp < 4; pp++)
        la[pp] = half ? 0ull : pack2(red[2 * pp], red[2 * pp + 1]);

    float* xsh  = (float*)(pool + 16384) + half * 4128;   // [16][258]
    int dbase = half * 256;
    int srow = t8 >> 2, sf4 = t8 & 3;
    const float4* xt4 = (const float4*)xt;
    int fidx = (dbase >> 2) + sf4;
    float4 v0 = xt4[(size_t)(srow      ) * 128 + fidx];
    float4 v1 = xt4[(size_t)(srow +  64) * 128 + fidx];
    float4 v2 = xt4[(size_t)(srow + 128) * 128 + fidx];
    float4 v3 = xt4[(size_t)(srow + 192) * 128 + fidx];

    for (int c0 = 0; c0 < 256; c0 += 16) {
        int dl0 = sf4 * 4;
        #pragma unroll
        for (int k = 0; k < 4; k++) {
            float vv0 = (k==0)?v0.x:(k==1)?v0.y:(k==2)?v0.z:v0.w;
            float vv1 = (k==0)?v1.x:(k==1)?v1.y:(k==2)?v1.z:v1.w;
            float vv2 = (k==0)?v2.x:(k==1)?v2.y:(k==2)?v2.z:v2.w;
            float vv3 = (k==0)?v3.x:(k==1)?v3.y:(k==2)?v3.z:v3.w;
            xsh[(dl0 + k) * 258 + srow      ] = vv0;
            xsh[(dl0 + k) * 258 + srow +  64] = vv1;
            xsh[(dl0 + k) * 258 + srow + 128] = vv2;
            xsh[(dl0 + k) * 258 + srow + 192] = vv3;
        }
        __syncthreads();
        if (c0 + 16 < 256) {
            int f = ((dbase + c0 + 16) >> 2) + sf4;
            v0 = xt4[(size_t)(srow      ) * 128 + f];
            v1 = xt4[(size_t)(srow +  64) * 128 + f];
            v2 = xt4[(size_t)(srow + 128) * 128 + f];
            v3 = xt4[(size_t)(srow + 192) * 128 + f];
        }
        #pragma unroll
        for (int dl = 0; dl < 16; dl++) {
            float xv = xsh[dl * 258 + t8];                 // conflict-free
            u64t xd = pack2(xv, xv);
            const ulonglong2* Pp =
                (const ulonglong2*)&Psp[(dbase + c0 + dl) * 4];
            ulonglong2 p0 = Pp[0], p1 = Pp[1];             // broadcast LDS.128
            fma2(la[0], xd, p0.x); fma2(la[1], xd, p0.y);
            fma2(la[2], xd, p1.x); fma2(la[3], xd, p1.y);
        }
        __syncthreads();
    }
    #pragma unroll
    for (int pp = 0; pp < 4; pp++) {
        float2 f = unpack2(la[pp]);
        Lp[half * 2048 + (2 * pp)     * 256 + t8] = f.x;
        Lp[half * 2048 + (2 * pp + 1) * 256 + t8] = f.y;
    }
    __syncthreads();

    // ---- softmax
    int wid = tid >> 5, lane = tid & 31;
    if (wid < 8) {
        float m = -1e30f;
        for (int i = lane; i < 256; i += 32) {
            float v = Lp[wid * 256 + i] + Lp[2048 + wid * 256 + i];
            Lp[wid * 256 + i] = v;
            m = fmaxf(m, v);
        }
        #pragma unroll
        for (int o = 16; o > 0; o >>= 1)
            m = fmaxf(m, __shfl_xor_sync(0xffffffffu, m, o));
        if (lane == 0) red[wid] = m;
    }
    __syncthreads();
    {
        #pragma unroll
        for (int jj = 0; jj < 2; jj++) {
            int j = half * 2 + jj;
            float e0 = __expf(Lp[(2 * j)     * 256 + t8] - red[2 * j]);
            float e1 = __expf(Lp[(2 * j + 1) * 256 + t8] - red[2 * j + 1]);
            ulonglong2 v; v.x = pack2(e0, e0); v.y = pack2(e1, e1);
            Es2[j * 256 + t8] = v;
        }
    }
    __syncthreads();
    if (wid < 8) {
        int j = wid >> 1, hi = wid & 1;
        float s = 0.f;
        for (int i = lane; i < 256; i += 32) {
            ulonglong2 v = Es2[j * 256 + i];
            s += unpack2(hi ? v.y : v.x).x;
        }
        #pragma unroll
        for (int o = 16; o > 0; o >>= 1) s += __shfl_xor_sync(0xffffffffu, s, o);
        if (lane == 0) red[8 + wid] = 1.0f / s;
    }
    __syncthreads();

    // ---- phase 2: thread = (f4-column, head-half, token-half)
    int f4c = tid & 127;
    int hh  = (tid >> 7) & 1;
    int th  = tid >> 8;
    u64t acc[8];
    #pragma unroll
    for (int k = 0; k < 8; k++) acc[k] = 0ull;

    const ulonglong2* x4u = (const ulonglong2*)xt + f4c;
    const ulonglong2* Ep0 = &Es2[(2 * hh)     * 256];
    const ulonglong2* Ep1 = &Es2[(2 * hh + 1) * 256];
    int tok0 = th * 128;
    #pragma unroll 8
    for (int nn = 0; nn < 128; nn++) {
        int tok = tok0 + nn;
        ulonglong2 xv = x4u[(size_t)tok * 128];
        ulonglong2 e0 = Ep0[tok];
        ulonglong2 e1 = Ep1[tok];
        fma2(acc[0], e0.x, xv.x); fma2(acc[1], e0.x, xv.y);
        fma2(acc[2], e0.y, xv.x); fma2(acc[3], e0.y, xv.y);
        fma2(acc[4], e1.x, xv.x); fma2(acc[5], e1.x, xv.y);
        fma2(acc[6], e1.y, xv.x); fma2(acc[7], e1.y, xv.y);
    }
    if (th == 1) {
        #pragma unroll
        for (int k = 0; k < 4; k++) {
            ulonglong2 v; v.x = acc[2 * k]; v.y = acc[2 * k + 1];
            Yp[(hh * 128 + f4c) * 4 + k] = v;
        }
    }
    __syncthreads();
    if (th == 0) {
        #pragma unroll
        for (int k = 0; k < 4; k++) {
            int h = 4 * hh + k;
            ulonglong2 v = Yp[(hh * 128 + f4c) * 4 + k];
            float2 a0 = unpack2(acc[2 * k]),     b0 = unpack2(v.x);
            float2 a1 = unpack2(acc[2 * k + 1]), b1 = unpack2(v.y);
            float inv = red[8 + h];
            float4 o;
            o.x = (a0.x + b0.x) * inv; o.y = (a0.y + b0.y) * inv;
            o.z = (a1.x + b1.x) * inv; o.w = (a1.y + b1.y) * inv;
            ((float4*)(g_Y + ((size_t)t * NH + h) * DMODEL))[f4c] = o;
        }
    }
}

// ---------------------------------------------------------------------------
extern "C" void kernel_launch(void* const* d_in, const int* in_sizes, int n_in,
                              void* d_out, int out_size)
{
    const float* x  = (const float*)d_in[0];
    const float* Wq = (const float*)d_in[1];
    const float* bq = (const float*)d_in[2];
    const float* Wk = (const float*)d_in[3];
    const float* bk = (const float*)d_in[4];
    const float* Wv = (const float*)d_in[5];
    const float* bv = (const float*)d_in[6];
    const float* Wo = (const float*)d_in[7];
    const float* bo = (const float*)d_in[8];
    float* out = (float*)d_out;
    (void)in_sizes; (void)n_in; (void)out_size;

    void *pQ, *pY, *pC;
    cudaGetSymbolAddress(&pQ, g_Q);
    cudaGetSymbolAddress(&pY, g_Y);
    cudaGetSymbolAddress(&pC, g_ctx);

    cudaFuncSetAttribute(attn_k, cudaFuncAttributeMaxDynamicSharedMemorySize,
                         ATTN_SMEM);

    // mine #0: zero split-K destinations (g_Q, g_ctx, out)
    zero_k<<<128, 256>>>((float*)pQ, (float*)pC, out);

    // mine #1: K1: Q = X0 @ Wq + bq   (split-K x4 -> 256 CTAs)
    gemm_k<<<dim3(8, 8, 4), 256>>>(
        x, (size_t)(NTOK * DMODEL), 0,
        Wq, DMODEL, 0, bq, 0,
        (float*)pQ, DMODEL, 0, 1);

    // mine #2: K2: all 8 heads (1024 CTAs)
    pproj_k<<<dim3(16, 8, NH), 256>>>(Wk);

    // mine #3: K3: per-tile attention -> g_Y   (PROFILED)
    attn_k<<<TT, 512, ATTN_SMEM>>>(x, bk);

    // mine #4: K4: ctx_h = Y_h @ Wv[:,h] + bv_h   (split-K x4 -> 256 CTAs)
    gemm_k<<<dim3(8, 1, 32), 256>>>(
        (const float*)pY, (size_t)(NH * DMODEL), (size_t)DMODEL,
        Wv, DMODEL, HD, bv, HD,
        (float*)pC, DMODEL, HD, NH);

    // mine #5: K5: out = ctx @ Wo + bo   (split-K x4 -> 256 CTAs)
    gemm_k<<<dim3(8, 8, 4), 256>>>(
        (const float*)pC, (size_t)DMODEL, 0,
        Wo, DMODEL, 0, bo, 0,
        out, DMODEL, 0, 1);
}